// round 5
// baseline (speedup 1.0000x reference)
#include <cuda_runtime.h>
#include <cstdint>
#include <cstddef>

#define SEQ   512
#define BATCH 64
#define INDIM 128
#define HDIM  512

#define CL    8            // CTAs per cluster (H split)
#define NG    16           // batch groups = clusters
#define BROWS 4            // batch rows per group (64/16)
#define JC    (HDIM / CL)  // 64 j columns per CTA
#define RT    256

typedef unsigned long long u64;

__device__ __forceinline__ u64 fma2(u64 a, u64 b, u64 c) {
    u64 d;
    asm("fma.rn.f32x2 %0, %1, %2, %3;" : "=l"(d) : "l"(a), "l"(b), "l"(c));
    return d;
}
__device__ __forceinline__ uint32_t smem_u32(const void* p) {
    uint32_t a;
    asm("{ .reg .u64 t; cvta.to.shared.u64 t, %1; cvt.u32.u64 %0, t; }" : "=r"(a) : "l"(p));
    return a;
}
__device__ __forceinline__ uint32_t mapa_u32(uint32_t a, uint32_t r) {
    uint32_t d;
    asm("mapa.shared::cluster.u32 %0, %1, %2;" : "=r"(d) : "r"(a), "r"(r));
    return d;
}
__device__ __forceinline__ void st_cluster_b64(uint32_t a, u64 v) {
    asm volatile("st.shared::cluster.b64 [%0], %1;" :: "r"(a), "l"(v) : "memory");
}
#define CLUSTER_SYNC() do { \
    asm volatile("barrier.cluster.arrive.aligned;" ::: "memory"); \
    asm volatile("barrier.cluster.wait.aligned;"   ::: "memory"); \
} while (0)

// ---------------------------------------------------------------------------
// xi kernel: out[s][b][h] = x[s][b][:] . Wi[h][:] + bi[h] + bh[h]
// Block tile 64 (s*b) rows x 128 h; thread tile 8x4; packed f32x2 over
// k-pairs. SMEM row stride 130 floats (even -> aligned u64, 65-u64 stride
// -> conflict-free 64-bit LDS).
// ---------------------------------------------------------------------------
__global__ __launch_bounds__(256) void xi_kernel(
    const float* __restrict__ x, const float* __restrict__ Wi,
    const float* __restrict__ bi, const float* __restrict__ bh,
    float* __restrict__ out)
{
    extern __shared__ float sm[];
    float* ws = sm;               // [128][130]
    float* xs = sm + 128 * 130;   // [64][130]

    const int tid = threadIdx.x;
    const int sb0 = blockIdx.x * 64;   // 512 tiles over 32768 rows
    const int h0  = blockIdx.y * 128;  // 4 tiles over 512 h

    for (int i = tid; i < 128 * INDIM; i += 256) {
        int r = i >> 7, k = i & 127;
        ws[r * 130 + k] = Wi[(h0 + r) * INDIM + k];
    }
    for (int i = tid; i < 64 * INDIM; i += 256) {
        int r = i >> 7, k = i & 127;
        xs[r * 130 + k] = x[(size_t)(sb0 + r) * INDIM + k];
    }
    __syncthreads();

    const int w  = tid >> 5;   // warp 0..7 -> sb rows w*8 .. +7
    const int tx = tid & 31;   // h = j*32 + tx

    u64 acc2[8][4];
#pragma unroll
    for (int i = 0; i < 8; i++)
#pragma unroll
        for (int j = 0; j < 4; j++) acc2[i][j] = 0ull;

    const u64* xb2 = (const u64*)xs + (w * 8) * 65;
    const u64* wb2 = (const u64*)ws;

#pragma unroll 4
    for (int kp = 0; kp < 64; kp++) {
        u64 xv[8], wv[4];
#pragma unroll
        for (int i = 0; i < 8; i++) xv[i] = xb2[i * 65 + kp];
#pragma unroll
        for (int j = 0; j < 4; j++) wv[j] = wb2[(j * 32 + tx) * 65 + kp];
#pragma unroll
        for (int i = 0; i < 8; i++)
#pragma unroll
            for (int j = 0; j < 4; j++) acc2[i][j] = fma2(xv[i], wv[j], acc2[i][j]);
    }

#pragma unroll
    for (int j = 0; j < 4; j++) {
        int h = h0 + j * 32 + tx;
        float b = bi[h] + bh[h];
#pragma unroll
        for (int i = 0; i < 8; i++) {
            float2 a = *reinterpret_cast<float2*>(&acc2[i][j]);
            out[(size_t)(sb0 + w * 8 + i) * HDIM + h] = a.x + a.y + b;
        }
    }
}

// ---------------------------------------------------------------------------
// Persistent recurrent kernel with cluster/DSMEM exchange.
// 16 clusters (batch groups of 4 rows) x 8 CTAs (64 j-cols each).
// Wh tile [64][512] (128KB) resident in SMEM. Each step: compute own h chunk
// from the LOCAL full-h SMEM copy, push pair-packed results into all 8 peers'
// ping-pong h buffers via st.shared::cluster, one barrier.cluster per step.
// Warp tile 4b x 8j, lane = k-pair slice, packed fma.rn.f32x2, 5-stage
// shuffle butterfly for the split-k-32 reduction.
// ---------------------------------------------------------------------------
__global__ __launch_bounds__(RT, 1) __cluster_dims__(CL, 1, 1)
void rnn_kernel(const float* __restrict__ Wh, float* __restrict__ out)
{
    extern __shared__ float sm[];
    float* sWh  = sm;              // [JC][HDIM]       128 KB
    float* hbuf = sm + JC * HDIM;  // [2][BROWS][HDIM]  16 KB ping-pong

    const int tid = threadIdx.x;
    uint32_t rank;
    asm("mov.u32 %0, %%cluster_ctarank;" : "=r"(rank));
    const int g = blockIdx.x / CL;   // batch group 0..15

    // load this CTA's Wh rows [rank*JC, +JC) once
    {
        const float4* src = (const float4*)(Wh + (size_t)rank * JC * HDIM);
        float4* dst = (float4*)sWh;
        for (int i = tid; i < JC * HDIM / 4; i += RT) dst[i] = src[i];
    }
    __syncthreads();

    const int w    = tid >> 5;          // warp 0..7 -> j octet w*8..+7
    const int lane = tid & 31;          // k-pair slice
    const int b    = lane >> 3;         // 0..3 (output row after butterfly)
    const int ojl  = rank * JC + w * 8 + (lane & 7);  // j in 0..511
    const int ob   = g * BROWS + b;     // global batch row

    const u64* wb2 = (const u64*)sWh + (w * 8) * (HDIM / 2) + lane;

    // peer SMEM base addresses (mapa once); start push sequence at own rank
    uint32_t hb_base = smem_u32(hbuf);
    uint32_t peer[CL];
#pragma unroll
    for (int r = 0; r < CL; r++) peer[r] = mapa_u32(hb_base, (rank + r) & (CL - 1));

    for (int t = 1; t <= SEQ; t++) {
        const size_t oidx = (size_t)(t - 1) * (BATCH * HDIM) + (size_t)ob * HDIM + ojl;
        const float xiv = __ldg(out + oidx);   // xi + bi + bh, precomputed

        float sum = 0.f;
        if (t > 1) {
            const u64* hp = (const u64*)(hbuf + ((t - 1) & 1) * BROWS * HDIM) + lane;

            u64 acc[4][8];
#pragma unroll
            for (int i = 0; i < 4; i++)
#pragma unroll
                for (int j = 0; j < 8; j++) acc[i][j] = 0ull;

#pragma unroll
            for (int d = 0; d < 8; d++) {   // k = d*64 + lane*2
                u64 hv[4], wv[8];
#pragma unroll
                for (int i = 0; i < 4; i++) hv[i] = hp[i * (HDIM / 2) + d * 32];
#pragma unroll
                for (int j = 0; j < 8; j++) wv[j] = wb2[j * (HDIM / 2) + d * 32];
#pragma unroll
                for (int i = 0; i < 4; i++)
#pragma unroll
                    for (int j = 0; j < 8; j++) acc[i][j] = fma2(hv[i], wv[j], acc[i][j]);
            }

            // collapse k-pairs, 5-stage shuffle butterfly (lane -> output lane)
            float v[32];
#pragma unroll
            for (int i = 0; i < 4; i++)
#pragma unroll
                for (int j = 0; j < 8; j++) {
                    float2 a = *reinterpret_cast<float2*>(&acc[i][j]);
                    v[i * 8 + j] = a.x + a.y;
                }
#pragma unroll
            for (int m = 0; m < 5; m++) {
                const int mb = (lane >> m) & 1;
#pragma unroll
                for (int j2 = 0; j2 < (16 >> m); j2++) {
                    float send = v[2 * j2 + 1 - mb];
                    float recv = __shfl_xor_sync(0xffffffffu, send, 1 << m);
                    v[j2] = v[2 * j2 + mb] + recv;
                }
            }
            sum = v[0];
        }

        const float hval = tanhf(sum + xiv);

        out[oidx] = hval;                                   // h_seq[t-1]
        if (t == SEQ)
            out[(size_t)SEQ * BATCH * HDIM + (size_t)ob * HDIM + ojl] = hval;

        // pair-pack (even lane carries j, j+1) and push to all 8 peers' SMEM,
        // rotated by own rank to spread receiver-side crossbar pressure
        float nxt = __shfl_down_sync(0xffffffffu, hval, 1);
        if (!(lane & 1)) {
            float2 p2 = make_float2(hval, nxt);
            u64 pv = *reinterpret_cast<u64*>(&p2);
            uint32_t off = (uint32_t)(((t & 1) * BROWS * HDIM + b * HDIM + ojl) * 4);
#pragma unroll
            for (int r = 0; r < CL; r++) st_cluster_b64(peer[r] + off, pv);
        }

        CLUSTER_SYNC();   // release own stores / acquire peers' for next step
    }
}

// ---------------------------------------------------------------------------
extern "C" void kernel_launch(void* const* d_in, const int* in_sizes, int n_in,
                              void* d_out, int out_size)
{
    const float* x  = (const float*)d_in[0];
    const float* Wi = (const float*)d_in[1];
    const float* bi = (const float*)d_in[2];
    const float* Wh = (const float*)d_in[3];
    const float* bh = (const float*)d_in[4];
    float* out = (float*)d_out;

    const int XI_SMEM  = (128 * 130 + 64 * 130) * 4;          // 99840 B
    const int RNN_SMEM = (JC * HDIM + 2 * BROWS * HDIM) * 4;  // 147456 B

    cudaFuncSetAttribute(xi_kernel,  cudaFuncAttributeMaxDynamicSharedMemorySize, XI_SMEM);
    cudaFuncSetAttribute(rnn_kernel, cudaFuncAttributeMaxDynamicSharedMemorySize, RNN_SMEM);

    // input projection (bi+bh folded) written into d_out's h_seq region
    xi_kernel<<<dim3(32768 / 64, HDIM / 128), 256, XI_SMEM>>>(x, Wi, bi, bh, out);
    // recurrence: 16 clusters x 8 CTAs, DSMEM h exchange, 1 cluster barrier/step
    rnn_kernel<<<NG * CL, RT, RNN_SMEM>>>(Wh, out);
}